// round 6
// baseline (speedup 1.0000x reference)
#include <cuda_runtime.h>
#include <cstdint>

// ---------------- Problem constants ----------------
#define NB    4096
#define SEQ   168
#define PRED  96
#define CF    64      // channels
#define KK    25      // decomp kernel taps
#define PAD   12
#define NQ    4
#define NL    3
#define NLAG  11

typedef unsigned long long u64;

// ---------------- Scratch (device globals; no allocation) ----------------
__device__ float4 g_G4[PRED * SEQ * (CF / 4)];   // G[p][j][c] float4 over c
__device__ float4 g_H4[PRED * SEQ * (CF / 4)];   // H[p][j][c]
__device__ float  g_mod[NB * PRED];
__device__ float  g_b0[PRED];
__device__ float  g_b1[PRED];

// ---------------- packed f32x2 helpers ----------------
__device__ __forceinline__ u64 pack2(float lo, float hi) {
    u64 r; asm("mov.b64 %0, {%1, %2};" : "=l"(r) : "f"(lo), "f"(hi)); return r;
}
__device__ __forceinline__ void fma2(u64& d, u64 a, u64 b) {
    asm("fma.rn.f32x2 %0, %1, %2, %0;" : "+l"(d) : "l"(a), "l"(b));
}
__device__ __forceinline__ void add2(u64& d, u64 a) {
    asm("add.rn.f32x2 %0, %0, %1;" : "+l"(d) : "l"(a));
}

// =====================================================================
// Quantum circuit helper
// =====================================================================
__device__ __forceinline__ void circuit_feats(const float* __restrict__ U,
                                              const float* cry, const float* sry,
                                              int pauli, float* feats)
{
    float sr[16], si[16];
    #pragma unroll
    for (int i = 0; i < 16; i++) { sr[i] = 0.f; si[i] = 0.f; }
    sr[0] = 1.f;

    #pragma unroll
    for (int l = 0; l < NL; l++) {
        #pragma unroll
        for (int q = 0; q < NQ; q++) {
            const int m = 8 >> q;
            const float cc = cry[q], ss = sry[q];
            #pragma unroll
            for (int g = 0; g < 8; g++) {
                const int i0 = ((g & ~(m - 1)) << 1) | (g & (m - 1));
                const int i1 = i0 | m;
                const float r0 = sr[i0], r1 = sr[i1];
                const float q0 = si[i0], q1 = si[i1];
                sr[i0] = cc * r0 - ss * r1;  sr[i1] = ss * r0 + cc * r1;
                si[i0] = cc * q0 - ss * q1;  si[i1] = ss * q0 + cc * q1;
            }
        }
        #pragma unroll
        for (int q = 0; q < NQ; q++) {
            const float* u = U + (l * NQ + q) * 8;
            const float u00r = u[0], u00i = u[1], u01r = u[2], u01i = u[3];
            const float u10r = u[4], u10i = u[5], u11r = u[6], u11i = u[7];
            const int m = 8 >> q;
            #pragma unroll
            for (int g = 0; g < 8; g++) {
                const int i0 = ((g & ~(m - 1)) << 1) | (g & (m - 1));
                const int i1 = i0 | m;
                const float a0r = sr[i0], a0i = si[i0];
                const float a1r = sr[i1], a1i = si[i1];
                sr[i0] = u00r * a0r - u00i * a0i + u01r * a1r - u01i * a1i;
                si[i0] = u00r * a0i + u00i * a0r + u01r * a1i + u01i * a1r;
                sr[i1] = u10r * a0r - u10i * a0i + u11r * a1r - u11i * a1i;
                si[i1] = u10r * a0i + u10i * a0r + u11r * a1i + u11i * a1r;
            }
        }
        #pragma unroll
        for (int q = 0; q < NQ; q++) {
            const int mc = 8 >> q;
            const int mt = 8 >> ((q + 1) & 3);
            #pragma unroll
            for (int i = 0; i < 16; i++) {
                if ((i & mc) && !(i & mt)) {
                    const int jx = i | mt;
                    float t0 = sr[i]; sr[i] = sr[jx]; sr[jx] = t0;
                    float t1 = si[i]; si[i] = si[jx]; si[jx] = t1;
                }
            }
        }
    }

    #pragma unroll
    for (int q = 0; q < NQ; q++) {
        const int m = 8 >> q;
        float acc = 0.f;
        #pragma unroll
        for (int g = 0; g < 8; g++) {
            const int i0 = ((g & ~(m - 1)) << 1) | (g & (m - 1));
            const int i1 = i0 | m;
            if (pauli == 0)      acc += sr[i0] * sr[i1] + si[i0] * si[i1];
            else if (pauli == 1) acc += sr[i0] * si[i1] - si[i0] * sr[i1];
            else acc += sr[i0] * sr[i0] + si[i0] * si[i0] - sr[i1] * sr[i1] - si[i1] * si[i1];
        }
        feats[q] = (pauli == 2) ? acc : 2.f * acc;
    }
}

// =====================================================================
// Fused small kernel: blocks [0, 4032) build G/H (prep), blocks
// [4032, 4048) run the quantum circuit + readout MLP -> g_mod.
// One launch instead of two serialized ones; softmax is warp-parallel.
// =====================================================================
#define PREP_BLOCKS (63 * CF)   // 4032

__global__ __launch_bounds__(256) void qres_small(
    const float* __restrict__ x,
    const float* __restrict__ dw,
    const float* __restrict__ tW,  const float* __restrict__ tb_,
    const float* __restrict__ sW,  const float* __restrict__ sb_,
    const float* __restrict__ alpha,
    const float* __restrict__ lW,  const float* __restrict__ lb,
    const float* __restrict__ wx,  const float* __restrict__ wy,
    const float* __restrict__ wz,
    const float* __restrict__ W1,  const float* __restrict__ b1v,
    const float* __restrict__ W2,  const float* __restrict__ b2v)
{
    const int bid = blockIdx.x;
    const int tid = threadIdx.x;

    if (bid < PREP_BLOCKS) {
        // ----------------- PREP path -----------------
        __shared__ float ker[KK];
        const int c     = bid & (CF - 1);
        const int chunk = bid >> 6;          // 0..62

        if (tid < 32) {
            const float val = (tid < KK) ? dw[c * KK + tid] : -1e30f;
            float mx = val;
            #pragma unroll
            for (int off = 16; off > 0; off >>= 1)
                mx = fmaxf(mx, __shfl_xor_sync(0xFFFFFFFFu, mx, off));
            float e = (tid < KK) ? expf(val - mx) : 0.f;
            float s = e;
            #pragma unroll
            for (int off = 16; off > 0; off >>= 1)
                s += __shfl_xor_sync(0xFFFFFFFFu, s, off);
            if (tid < KK) ker[tid] = e / s;
        }
        __syncthreads();

        const int idx = chunk * 256 + tid;
        if (idx >= PRED * SEQ) return;
        const int p = idx / SEQ;
        const int j = idx - p * SEQ;

        const float a  = 1.f / (1.f + expf(-alpha[0]));
        const float ia = 1.f - a;

        const float* tw = tW + p * SEQ;
        const float* sw = sW + p * SEQ;

        float accD = 0.f, accS = 0.f;
        if (j == 0) {
            #pragma unroll 1
            for (int k = 0; k <= PAD; k++) {
                const float kk = ker[k];
                for (int l = 0; l <= PAD - k; l++) {
                    accD += kk * (ia * tw[l] - a * sw[l]);
                    accS += kk * sw[l];
                }
            }
        } else if (j == SEQ - 1) {
            #pragma unroll 1
            for (int k = PAD; k < KK; k++) {
                const float kk = ker[k];
                for (int l = (SEQ - 1 + PAD) - k; l < SEQ; l++) {
                    accD += kk * (ia * tw[l] - a * sw[l]);
                    accS += kk * sw[l];
                }
            }
        } else {
            #pragma unroll
            for (int k = 0; k < KK; k++) {
                const int l = j + PAD - k;
                if (l >= 0 && l < SEQ) {
                    const float kk = ker[k];
                    accD += kk * (ia * tw[l] - a * sw[l]);
                    accS += kk * sw[l];
                }
            }
        }

        float* Gf = reinterpret_cast<float*>(g_G4);
        float* Hf = reinterpret_cast<float*>(g_H4);
        const float swj = sw[j];
        Gf[(p * SEQ + j) * CF + c] = a * swj + accD;
        Hf[(p * SEQ + j) * CF + c] = a * (swj - accS);

        if (c == 0 && idx < PRED) {
            g_b0[idx] = a * sb_[idx] + ia * tb_[idx];
            g_b1[idx] = a * sb_[idx];
        }
        return;
    }

    // ----------------- QUANTUM path -----------------
    __shared__ float Us[3][NL * NQ * 8];
    __shared__ float sW1[12 * 12], sb1[12], sW2[96 * 12], sb2[96];

    if (tid < 36) {
        const int t = tid / 12, rem = tid % 12;
        const int l = rem / 4, q = rem % 4;
        const float* w = (t == 0) ? wx : ((t == 1) ? wy : wz);
        const float phi = w[(l * NQ + q) * 3 + 0];
        const float th  = w[(l * NQ + q) * 3 + 1];
        const float om  = w[(l * NQ + q) * 3 + 2];
        float st, ct;  sincosf(0.5f * th, &st, &ct);
        float sap, cap; sincosf(0.5f * (phi + om), &sap, &cap);
        float sam, cam; sincosf(0.5f * (phi - om), &sam, &cam);
        float* U = &Us[t][rem * 8];
        U[0] =  cap * ct;  U[1] = -sap * ct;
        U[2] = -cam * st;  U[3] = -sam * st;
        U[4] =  cam * st;  U[5] = -sam * st;
        U[6] =  cap * ct;  U[7] =  sap * ct;
    }
    for (int i = tid; i < 144;  i += 256) sW1[i] = W1[i];
    for (int i = tid; i < 1152; i += 256) sW2[i] = W2[i];
    if (tid < 12) sb1[tid] = b1v[tid];
    if (tid < 96) sb2[tid] = b2v[tid];
    __syncthreads();

    const int b = (bid - PREP_BLOCKS) * 256 + tid;
    if (b >= NB) return;

    const int LAGS[NLAG] = {167, 166, 165, 164, 163, 162, 145, 144, 143, 1, 0};
    float lag[NLAG];
    const float* xb = x + (size_t)b * SEQ * CF + (CF - 1);
    #pragma unroll
    for (int i = 0; i < NLAG; i++) lag[i] = xb[LAGS[i] * CF];

    const float PI_F = 3.14159265358979323846f;
    float cry[NQ], sry[NQ];
    #pragma unroll
    for (int q = 0; q < NQ; q++) {
        float acc = lb[q];
        #pragma unroll
        for (int i = 0; i < NLAG; i++) acc += lag[i] * lW[q * NLAG + i];
        const float qin = tanhf(acc) * PI_F;
        sincosf(0.5f * qin, &sry[q], &cry[q]);
    }

    float feats[12];
    circuit_feats(&Us[0][0], cry, sry, 0, &feats[0]);
    circuit_feats(&Us[1][0], cry, sry, 1, &feats[4]);
    circuit_feats(&Us[2][0], cry, sry, 2, &feats[8]);

    float h[12];
    #pragma unroll
    for (int i = 0; i < 12; i++) {
        float acc = sb1[i];
        #pragma unroll
        for (int jj = 0; jj < 12; jj++) acc += feats[jj] * sW1[i * 12 + jj];
        h[i] = fmaxf(acc, 0.f);
    }
    #pragma unroll 4
    for (int p = 0; p < PRED; p++) {
        float acc = sb2[p];
        #pragma unroll
        for (int i = 0; i < 12; i++) acc += h[i] * sW2[p * 12 + i];
        g_mod[b * PRED + p] = tanhf(acc);
    }
}

// =====================================================================
// Kernel 2: main batched GEMM, packed f32x2 math.
//   out[b,p,c] = x.G + mod*(x.H) + b0[p] + mod*b1[p]
// Block tile: 64 b x 32 p x 4 c. Threads 256 = 16(b) x 16(p).
// Thread tile: 4 b x 2 p x 4 c (as 2x f32x2). K panels of 8, double buf.
// grid: (3 p-tiles, 16 c-groups, 64 b-tiles)
// =====================================================================
#define KP 8
#define NPANEL (SEQ / KP)   // 21
#define CG4 (CF / 4)        // 16

__global__ __launch_bounds__(256) void qres_main(const float* __restrict__ x,
                                                 float* __restrict__ out)
{
    const int pt = blockIdx.x;
    const int cg = blockIdx.y;
    const int bt = blockIdx.z;
    const int b0 = bt * 64;
    const int p0 = pt * 32;

    const int tid = threadIdx.x;
    const int tb = tid & 15;
    const int tp = tid >> 4;

    __shared__ ulonglong2 Xs[2][KP][64];
    __shared__ ulonglong2 Gs[2][KP][32];
    __shared__ ulonglong2 Hs[2][KP][32];

    const ulonglong2* xg = reinterpret_cast<const ulonglong2*>(x);
    const ulonglong2* Gg = reinterpret_cast<const ulonglong2*>(g_G4);
    const ulonglong2* Hg = reinterpret_cast<const ulonglong2*>(g_H4);

    u64 aG[4][2][2], aH[4][2][2];
    #pragma unroll
    for (int bi = 0; bi < 4; bi++)
        #pragma unroll
        for (int pi = 0; pi < 2; pi++) {
            aG[bi][pi][0] = 0ull; aG[bi][pi][1] = 0ull;
            aH[bi][pi][0] = 0ull; aH[bi][pi][1] = 0ull;
        }

    const int xk0 = tid >> 6;    // 0..3
    const int xb0 = tid & 63;    // 0..63
    const int gk  = tid >> 5;    // 0..7
    const int gp  = tid & 31;    // 0..31

    const ulonglong2* xp = xg + ((size_t)(b0 + xb0) * SEQ + xk0) * CG4 + cg;
    const ulonglong2* Gp = Gg + ((size_t)(p0 + gp) * SEQ + gk) * CG4 + cg;
    const ulonglong2* Hp = Hg + ((size_t)(p0 + gp) * SEQ + gk) * CG4 + cg;

    // prologue: panel 0 -> buffer 0
    Xs[0][xk0][xb0]     = xp[0];
    Xs[0][xk0 + 4][xb0] = xp[4 * CG4];
    Gs[0][gk][gp] = Gp[0];
    Hs[0][gk][gp] = Hp[0];
    xp += KP * CG4;  Gp += KP * CG4;  Hp += KP * CG4;
    __syncthreads();

    for (int pn = 0; pn < NPANEL; pn++) {
        const int buf = pn & 1;
        ulonglong2 rx0, rx1, rg, rh;
        const bool more = (pn + 1 < NPANEL);
        if (more) {
            rx0 = xp[0];
            rx1 = xp[4 * CG4];
            rg  = Gp[0];
            rh  = Hp[0];
            xp += KP * CG4;  Gp += KP * CG4;  Hp += KP * CG4;
        }

        #pragma unroll
        for (int kj = 0; kj < KP; kj++) {
            ulonglong2 xf[4], gf[2], hf[2];
            #pragma unroll
            for (int i = 0; i < 4; i++) xf[i] = Xs[buf][kj][tb + 16 * i];
            #pragma unroll
            for (int i = 0; i < 2; i++) { gf[i] = Gs[buf][kj][tp + 16 * i];
                                          hf[i] = Hs[buf][kj][tp + 16 * i]; }
            #pragma unroll
            for (int bi = 0; bi < 4; bi++)
                #pragma unroll
                for (int pi = 0; pi < 2; pi++) {
                    fma2(aG[bi][pi][0], xf[bi].x, gf[pi].x);
                    fma2(aG[bi][pi][1], xf[bi].y, gf[pi].y);
                    fma2(aH[bi][pi][0], xf[bi].x, hf[pi].x);
                    fma2(aH[bi][pi][1], xf[bi].y, hf[pi].y);
                }
        }

        if (more) {
            const int nb = buf ^ 1;
            Xs[nb][xk0][xb0]     = rx0;
            Xs[nb][xk0 + 4][xb0] = rx1;
            Gs[nb][gk][gp] = rg;
            Hs[nb][gk][gp] = rh;
            __syncthreads();
        }
    }

    // epilogue (packed)
    ulonglong2* og = reinterpret_cast<ulonglong2*>(out);
    #pragma unroll
    for (int bi = 0; bi < 4; bi++) {
        const int b = b0 + tb + 16 * bi;
        #pragma unroll
        for (int pi = 0; pi < 2; pi++) {
            const int p = p0 + tp + 16 * pi;
            const float m   = g_mod[b * PRED + p];
            const float add = g_b0[p] + m * g_b1[p];
            const u64 m2  = pack2(m, m);
            const u64 ad2 = pack2(add, add);
            u64 r0 = aG[bi][pi][0], r1 = aG[bi][pi][1];
            fma2(r0, m2, aH[bi][pi][0]);
            fma2(r1, m2, aH[bi][pi][1]);
            add2(r0, ad2);
            add2(r1, ad2);
            ulonglong2 st; st.x = r0; st.y = r1;
            og[((size_t)b * PRED + p) * CG4 + cg] = st;
        }
    }
}

// =====================================================================
// Launch
// metadata order: x, decomp_w, trend_W, trend_b, seas_W, seas_b,
//                 lagc_W, lagc_b, res_wx, res_wy, res_wz,
//                 ro_W1, ro_b1, ro_W2, ro_b2, alpha
// =====================================================================
extern "C" void kernel_launch(void* const* d_in, const int* in_sizes, int n_in,
                              void* d_out, int out_size)
{
    const float* x      = (const float*)d_in[0];
    const float* dw     = (const float*)d_in[1];
    const float* tW     = (const float*)d_in[2];
    const float* tb_    = (const float*)d_in[3];
    const float* sW     = (const float*)d_in[4];
    const float* sb_    = (const float*)d_in[5];
    const float* lagcW  = (const float*)d_in[6];
    const float* lagcb  = (const float*)d_in[7];
    const float* wx     = (const float*)d_in[8];
    const float* wy     = (const float*)d_in[9];
    const float* wz     = (const float*)d_in[10];
    const float* roW1   = (const float*)d_in[11];
    const float* rob1   = (const float*)d_in[12];
    const float* roW2   = (const float*)d_in[13];
    const float* rob2   = (const float*)d_in[14];
    const float* alpha  = (const float*)d_in[15];
    float* out = (float*)d_out;

    qres_small<<<PREP_BLOCKS + NB / 256, 256>>>(
        x, dw, tW, tb_, sW, sb_, alpha,
        lagcW, lagcb, wx, wy, wz, roW1, rob1, roW2, rob2);
    qres_main<<<dim3(3, CF / 4, NB / 64), 256>>>(x, out);
}

// round 8
// speedup vs baseline: 1.0084x; 1.0084x over previous
#include <cuda_runtime.h>
#include <cstdint>

// ---------------- Problem constants ----------------
#define NB    4096
#define SEQ   168
#define PRED  96
#define CF    64
#define KK    25
#define PAD   12
#define NQ    4
#define NL    3
#define NLAG  11

typedef unsigned long long u64;

// ---------------- Scratch ----------------
__device__ float4 g_G4[PRED * SEQ * (CF / 4)];   // G[p][j][c] float4 over c
__device__ float4 g_H4[PRED * SEQ * (CF / 4)];   // H[p][j][c]
__device__ float  g_mod[NB * PRED];
__device__ float  g_b0[PRED];
__device__ float  g_b1[PRED];

// ---------------- packed f32x2 helpers ----------------
__device__ __forceinline__ u64 pack2(float lo, float hi) {
    u64 r; asm("mov.b64 %0, {%1, %2};" : "=l"(r) : "f"(lo), "f"(hi)); return r;
}
__device__ __forceinline__ void fma2(u64& d, u64 a, u64 b) {
    asm("fma.rn.f32x2 %0, %1, %2, %0;" : "+l"(d) : "l"(a), "l"(b));
}
__device__ __forceinline__ void add2(u64& d, u64 a) {
    asm("add.rn.f32x2 %0, %0, %1;" : "+l"(d) : "l"(a));
}

// ---------------- cp.async helpers ----------------
__device__ __forceinline__ void cp16(uint32_t smem_dst, const void* gptr) {
    asm volatile("cp.async.cg.shared.global [%0], [%1], 16;"
                 :: "r"(smem_dst), "l"(__cvta_generic_to_global(gptr)) : "memory");
}
__device__ __forceinline__ void cp_commit() {
    asm volatile("cp.async.commit_group;" ::: "memory");
}
__device__ __forceinline__ void cp_wait0() {
    asm volatile("cp.async.wait_group 0;" ::: "memory");
}

// =====================================================================
// Quantum circuit helper
// =====================================================================
__device__ __forceinline__ void circuit_feats(const float* __restrict__ U,
                                              const float* cry, const float* sry,
                                              int pauli, float* feats)
{
    float sr[16], si[16];
    #pragma unroll
    for (int i = 0; i < 16; i++) { sr[i] = 0.f; si[i] = 0.f; }
    sr[0] = 1.f;

    #pragma unroll
    for (int l = 0; l < NL; l++) {
        #pragma unroll
        for (int q = 0; q < NQ; q++) {
            const int m = 8 >> q;
            const float cc = cry[q], ss = sry[q];
            #pragma unroll
            for (int g = 0; g < 8; g++) {
                const int i0 = ((g & ~(m - 1)) << 1) | (g & (m - 1));
                const int i1 = i0 | m;
                const float r0 = sr[i0], r1 = sr[i1];
                const float q0 = si[i0], q1 = si[i1];
                sr[i0] = cc * r0 - ss * r1;  sr[i1] = ss * r0 + cc * r1;
                si[i0] = cc * q0 - ss * q1;  si[i1] = ss * q0 + cc * q1;
            }
        }
        #pragma unroll
        for (int q = 0; q < NQ; q++) {
            const float* u = U + (l * NQ + q) * 8;
            const float u00r = u[0], u00i = u[1], u01r = u[2], u01i = u[3];
            const float u10r = u[4], u10i = u[5], u11r = u[6], u11i = u[7];
            const int m = 8 >> q;
            #pragma unroll
            for (int g = 0; g < 8; g++) {
                const int i0 = ((g & ~(m - 1)) << 1) | (g & (m - 1));
                const int i1 = i0 | m;
                const float a0r = sr[i0], a0i = si[i0];
                const float a1r = sr[i1], a1i = si[i1];
                sr[i0] = u00r * a0r - u00i * a0i + u01r * a1r - u01i * a1i;
                si[i0] = u00r * a0i + u00i * a0r + u01r * a1i + u01i * a1r;
                sr[i1] = u10r * a0r - u10i * a0i + u11r * a1r - u11i * a1i;
                si[i1] = u10r * a0i + u10i * a0r + u11r * a1i + u11i * a1r;
            }
        }
        #pragma unroll
        for (int q = 0; q < NQ; q++) {
            const int mc = 8 >> q;
            const int mt = 8 >> ((q + 1) & 3);
            #pragma unroll
            for (int i = 0; i < 16; i++) {
                if ((i & mc) && !(i & mt)) {
                    const int jx = i | mt;
                    float t0 = sr[i]; sr[i] = sr[jx]; sr[jx] = t0;
                    float t1 = si[i]; si[i] = si[jx]; si[jx] = t1;
                }
            }
        }
    }

    #pragma unroll
    for (int q = 0; q < NQ; q++) {
        const int m = 8 >> q;
        float acc = 0.f;
        #pragma unroll
        for (int g = 0; g < 8; g++) {
            const int i0 = ((g & ~(m - 1)) << 1) | (g & (m - 1));
            const int i1 = i0 | m;
            if (pauli == 0)      acc += sr[i0] * sr[i1] + si[i0] * si[i1];
            else if (pauli == 1) acc += sr[i0] * si[i1] - si[i0] * sr[i1];
            else acc += sr[i0] * sr[i0] + si[i0] * si[i0] - sr[i1] * sr[i1] - si[i1] * si[i1];
        }
        feats[q] = (pauli == 2) ? acc : 2.f * acc;
    }
}

// =====================================================================
// Fused small kernel.
//  blocks [0, 6144): prep, one (p, c) pair each; tw/sw rows in smem.
//  blocks [6144, 6160): quantum circuit + readout MLP -> g_mod.
// =====================================================================
#define PREP_BLOCKS (PRED * CF)   // 6144

__global__ __launch_bounds__(256) void qres_small(
    const float* __restrict__ x,
    const float* __restrict__ dw,
    const float* __restrict__ tW,  const float* __restrict__ tb_,
    const float* __restrict__ sW,  const float* __restrict__ sb_,
    const float* __restrict__ alpha,
    const float* __restrict__ lW,  const float* __restrict__ lb,
    const float* __restrict__ wx,  const float* __restrict__ wy,
    const float* __restrict__ wz,
    const float* __restrict__ W1,  const float* __restrict__ b1v,
    const float* __restrict__ W2,  const float* __restrict__ b2v)
{
    const int bid = blockIdx.x;
    const int tid = threadIdx.x;

    if (bid < PREP_BLOCKS) {
        // ----------------- PREP path -----------------
        __shared__ float ker[32];
        __shared__ float twsh[SEQ], swsh[SEQ];
        const int p = bid >> 6;
        const int c = bid & (CF - 1);

        if (tid < 32) {
            const float val = (tid < KK) ? dw[c * KK + tid] : -1e30f;
            float mx = val;
            #pragma unroll
            for (int off = 16; off > 0; off >>= 1)
                mx = fmaxf(mx, __shfl_xor_sync(0xFFFFFFFFu, mx, off));
            float e = (tid < KK) ? expf(val - mx) : 0.f;
            float s = e;
            #pragma unroll
            for (int off = 16; off > 0; off >>= 1)
                s += __shfl_xor_sync(0xFFFFFFFFu, s, off);
            if (tid < 32) ker[tid] = (tid < KK) ? (e / s) : 0.f;
        }
        if (tid < SEQ) {
            twsh[tid] = tW[p * SEQ + tid];
            swsh[tid] = sW[p * SEQ + tid];
        }
        __syncthreads();

        const int j = tid;
        if (j >= SEQ) return;

        const float a  = 1.f / (1.f + expf(-alpha[0]));
        const float ia = 1.f - a;

        float accD = 0.f, accS = 0.f;
        if (j == 0) {
            #pragma unroll 1
            for (int k = 0; k <= PAD; k++) {
                const float kk = ker[k];
                for (int l = 0; l <= PAD - k; l++) {
                    accD += kk * (ia * twsh[l] - a * swsh[l]);
                    accS += kk * swsh[l];
                }
            }
        } else if (j == SEQ - 1) {
            #pragma unroll 1
            for (int k = PAD; k < KK; k++) {
                const float kk = ker[k];
                for (int l = (SEQ - 1 + PAD) - k; l < SEQ; l++) {
                    accD += kk * (ia * twsh[l] - a * swsh[l]);
                    accS += kk * swsh[l];
                }
            }
        } else {
            #pragma unroll
            for (int k = 0; k < KK; k++) {
                const int l = j + PAD - k;
                if (l >= 0 && l < SEQ) {
                    const float kk = ker[k];
                    accD += kk * (ia * twsh[l] - a * swsh[l]);
                    accS += kk * swsh[l];
                }
            }
        }

        float* Gf = reinterpret_cast<float*>(g_G4);
        float* Hf = reinterpret_cast<float*>(g_H4);
        const float swj = swsh[j];
        Gf[(p * SEQ + j) * CF + c] = a * swj + accD;
        Hf[(p * SEQ + j) * CF + c] = a * (swj - accS);

        if (c == 0 && j == 0) {
            g_b0[p] = a * sb_[p] + ia * tb_[p];
            g_b1[p] = a * sb_[p];
        }
        return;
    }

    // ----------------- QUANTUM path -----------------
    __shared__ float Us[3][NL * NQ * 8];
    __shared__ float sW1[12 * 12], sb1[12], sW2[96 * 12], sb2[96];

    if (tid < 36) {
        const int t = tid / 12, rem = tid % 12;
        const int l = rem / 4, q = rem % 4;
        const float* w = (t == 0) ? wx : ((t == 1) ? wy : wz);
        const float phi = w[(l * NQ + q) * 3 + 0];
        const float th  = w[(l * NQ + q) * 3 + 1];
        const float om  = w[(l * NQ + q) * 3 + 2];
        float st, ct;  sincosf(0.5f * th, &st, &ct);
        float sap, cap; sincosf(0.5f * (phi + om), &sap, &cap);
        float sam, cam; sincosf(0.5f * (phi - om), &sam, &cam);
        float* U = &Us[t][rem * 8];
        U[0] =  cap * ct;  U[1] = -sap * ct;
        U[2] = -cam * st;  U[3] = -sam * st;
        U[4] =  cam * st;  U[5] = -sam * st;
        U[6] =  cap * ct;  U[7] =  sap * ct;
    }
    for (int i = tid; i < 144;  i += 256) sW1[i] = W1[i];
    for (int i = tid; i < 1152; i += 256) sW2[i] = W2[i];
    if (tid < 12) sb1[tid] = b1v[tid];
    if (tid < 96) sb2[tid] = b2v[tid];
    __syncthreads();

    const int b = (bid - PREP_BLOCKS) * 256 + tid;
    if (b >= NB) return;

    const int LAGS[NLAG] = {167, 166, 165, 164, 163, 162, 145, 144, 143, 1, 0};
    float lag[NLAG];
    const float* xb = x + (size_t)b * SEQ * CF + (CF - 1);
    #pragma unroll
    for (int i = 0; i < NLAG; i++) lag[i] = xb[LAGS[i] * CF];

    const float PI_F = 3.14159265358979323846f;
    float cry[NQ], sry[NQ];
    #pragma unroll
    for (int q = 0; q < NQ; q++) {
        float acc = lb[q];
        #pragma unroll
        for (int i = 0; i < NLAG; i++) acc += lag[i] * lW[q * NLAG + i];
        const float qin = tanhf(acc) * PI_F;
        sincosf(0.5f * qin, &sry[q], &cry[q]);
    }

    float feats[12];
    circuit_feats(&Us[0][0], cry, sry, 0, &feats[0]);
    circuit_feats(&Us[1][0], cry, sry, 1, &feats[4]);
    circuit_feats(&Us[2][0], cry, sry, 2, &feats[8]);

    float h[12];
    #pragma unroll
    for (int i = 0; i < 12; i++) {
        float acc = sb1[i];
        #pragma unroll
        for (int jj = 0; jj < 12; jj++) acc += feats[jj] * sW1[i * 12 + jj];
        h[i] = fmaxf(acc, 0.f);
    }
    #pragma unroll 4
    for (int p = 0; p < PRED; p++) {
        float acc = sb2[p];
        #pragma unroll
        for (int i = 0; i < 12; i++) acc += h[i] * sW2[p * 12 + i];
        g_mod[b * PRED + p] = tanhf(acc);
    }
}

// =====================================================================
// Main GEMM: 512 threads, block tile 64b x 96p x 4c, thread tile 4b x 3p x 4c.
// cp.async double-buffered K-panels of 4. f32x2 math.
// grid: (16 cg, 64 bt)
// =====================================================================
#define KP 4
#define NPANEL (SEQ / KP)   // 42
#define CG4 (CF / 4)        // 16

__global__ __launch_bounds__(512, 1) void qres_main(const float* __restrict__ x,
                                                    float* __restrict__ out)
{
    const int cg = blockIdx.x;   // 0..15
    const int bt = blockIdx.y;   // 0..63
    const int b0 = bt * 64;

    const int tid = threadIdx.x;
    const int tb = tid & 15;     // 0..15 (b)
    const int tp = tid >> 4;     // 0..31 (p)

    __shared__ ulonglong2 Xs[2][KP][64];
    __shared__ ulonglong2 Gs[2][KP][PRED];
    __shared__ ulonglong2 Hs[2][KP][PRED];

    const ulonglong2* xg = reinterpret_cast<const ulonglong2*>(x);
    const ulonglong2* Gg = reinterpret_cast<const ulonglong2*>(g_G4);
    const ulonglong2* Hg = reinterpret_cast<const ulonglong2*>(g_H4);

    u64 aG[4][3][2], aH[4][3][2];
    #pragma unroll
    for (int bi = 0; bi < 4; bi++)
        #pragma unroll
        for (int pi = 0; pi < 3; pi++) {
            aG[bi][pi][0] = 0ull; aG[bi][pi][1] = 0ull;
            aH[bi][pi][0] = 0ull; aH[bi][pi][1] = 0ull;
        }

    // loader roles
    const bool loadX = (tid < 256);
    const int xk0 = tid >> 6;          // 0..3 (valid when loadX)
    const int xb0 = tid & 63;
    const bool loadG = (tid >= 128);
    const int gt = tid - 128;          // 0..383
    const int gk = gt / PRED;          // 0..3
    const int gp = gt - gk * PRED;     // 0..95

    const ulonglong2* xp = xg + ((size_t)(b0 + xb0) * SEQ + xk0) * CG4 + cg;
    const ulonglong2* Gp = Gg + ((size_t)gp * SEQ + gk) * CG4 + cg;
    const ulonglong2* Hp = Hg + ((size_t)gp * SEQ + gk) * CG4 + cg;

    const uint32_t sX0 = (uint32_t)__cvta_generic_to_shared(&Xs[0][xk0][xb0]);
    const uint32_t sX1 = (uint32_t)__cvta_generic_to_shared(&Xs[1][xk0][xb0]);
    const uint32_t sG0 = (uint32_t)__cvta_generic_to_shared(&Gs[0][gk][gp]);
    const uint32_t sG1 = (uint32_t)__cvta_generic_to_shared(&Gs[1][gk][gp]);
    const uint32_t sH0 = (uint32_t)__cvta_generic_to_shared(&Hs[0][gk][gp]);
    const uint32_t sH1 = (uint32_t)__cvta_generic_to_shared(&Hs[1][gk][gp]);

    // prologue: panel 0 -> buffer 0
    if (loadX) cp16(sX0, xp);
    if (loadG) { cp16(sG0, Gp); cp16(sH0, Hp); }
    cp_commit();
    if (loadX) xp += KP * CG4;
    if (loadG) { Gp += KP * CG4; Hp += KP * CG4; }

    for (int pn = 0; pn < NPANEL; pn++) {
        const int buf = pn & 1;
        cp_wait0();
        __syncthreads();   // panel pn visible; previous compute on buf^1 done

        if (pn + 1 < NPANEL) {
            if (loadX) { cp16(buf ? sX0 : sX1, xp); xp += KP * CG4; }
            if (loadG) { cp16(buf ? sG0 : sG1, Gp); Gp += KP * CG4;
                         cp16(buf ? sH0 : sH1, Hp); Hp += KP * CG4; }
        }
        cp_commit();

        #pragma unroll
        for (int kj = 0; kj < KP; kj++) {
            ulonglong2 xf[4];
            #pragma unroll
            for (int bi = 0; bi < 4; bi++) xf[bi] = Xs[buf][kj][tb + 16 * bi];
            #pragma unroll
            for (int pi = 0; pi < 3; pi++) {
                const ulonglong2 gf = Gs[buf][kj][tp + 32 * pi];
                const ulonglong2 hf = Hs[buf][kj][tp + 32 * pi];
                #pragma unroll
                for (int bi = 0; bi < 4; bi++) {
                    fma2(aG[bi][pi][0], xf[bi].x, gf.x);
                    fma2(aG[bi][pi][1], xf[bi].y, gf.y);
                    fma2(aH[bi][pi][0], xf[bi].x, hf.x);
                    fma2(aH[bi][pi][1], xf[bi].y, hf.y);
                }
            }
        }
    }

    // epilogue
    ulonglong2* og = reinterpret_cast<ulonglong2*>(out);
    #pragma unroll
    for (int bi = 0; bi < 4; bi++) {
        const int b = b0 + tb + 16 * bi;
        #pragma unroll
        for (int pi = 0; pi < 3; pi++) {
            const int p = tp + 32 * pi;
            const float m   = g_mod[b * PRED + p];
            const float add = g_b0[p] + m * g_b1[p];
            const u64 m2  = pack2(m, m);
            const u64 ad2 = pack2(add, add);
            u64 r0 = aG[bi][pi][0], r1 = aG[bi][pi][1];
            fma2(r0, m2, aH[bi][pi][0]);
            fma2(r1, m2, aH[bi][pi][1]);
            add2(r0, ad2);
            add2(r1, ad2);
            ulonglong2 st; st.x = r0; st.y = r1;
            og[((size_t)b * PRED + p) * CG4 + cg] = st;
        }
    }
}

// =====================================================================
// Launch
// =====================================================================
extern "C" void kernel_launch(void* const* d_in, const int* in_sizes, int n_in,
                              void* d_out, int out_size)
{
    const float* x      = (const float*)d_in[0];
    const float* dw     = (const float*)d_in[1];
    const float* tW     = (const float*)d_in[2];
    const float* tb_    = (const float*)d_in[3];
    const float* sW     = (const float*)d_in[4];
    const float* sb_    = (const float*)d_in[5];
    const float* lagcW  = (const float*)d_in[6];
    const float* lagcb  = (const float*)d_in[7];
    const float* wx     = (const float*)d_in[8];
    const float* wy     = (const float*)d_in[9];
    const float* wz     = (const float*)d_in[10];
    const float* roW1   = (const float*)d_in[11];
    const float* rob1   = (const float*)d_in[12];
    const float* roW2   = (const float*)d_in[13];
    const float* rob2   = (const float*)d_in[14];
    const float* alpha  = (const float*)d_in[15];
    float* out = (float*)d_out;

    qres_small<<<PREP_BLOCKS + NB / 256, 256>>>(
        x, dw, tW, tb_, sW, sb_, alpha,
        lagcW, lagcb, wx, wy, wz, roW1, rob1, roW2, rob2);
    qres_main<<<dim3(CG4, NB / 64), 512>>>(x, out);
}

// round 9
// speedup vs baseline: 1.0110x; 1.0026x over previous
#include <cuda_runtime.h>
#include <cstdint>

// ---------------- Problem constants ----------------
#define NB    4096
#define SEQ   168
#define PRED  96
#define CF    64
#define KK    25
#define PAD   12
#define NQ    4
#define NL    3
#define NLAG  11

typedef unsigned long long u64;

// ---------------- Scratch ----------------
__device__ float4 g_G4[PRED * SEQ * (CF / 4)];   // G[p][j][c] float4 over c
__device__ float4 g_H4[PRED * SEQ * (CF / 4)];   // H[p][j][c]
__device__ float  g_mod[NB * PRED];
__device__ float  g_b0[PRED];
__device__ float  g_b1[PRED];

// ---------------- packed f32x2 helpers ----------------
__device__ __forceinline__ u64 pack2(float lo, float hi) {
    u64 r; asm("mov.b64 %0, {%1, %2};" : "=l"(r) : "f"(lo), "f"(hi)); return r;
}
__device__ __forceinline__ void fma2(u64& d, u64 a, u64 b) {
    asm("fma.rn.f32x2 %0, %1, %2, %0;" : "+l"(d) : "l"(a), "l"(b));
}
__device__ __forceinline__ void add2(u64& d, u64 a) {
    asm("add.rn.f32x2 %0, %0, %1;" : "+l"(d) : "l"(a));
}

// ---------------- cp.async helpers ----------------
__device__ __forceinline__ void cp16(uint32_t smem_dst, const void* gptr) {
    asm volatile("cp.async.cg.shared.global [%0], [%1], 16;"
                 :: "r"(smem_dst), "l"(__cvta_generic_to_global(gptr)) : "memory");
}
__device__ __forceinline__ void cp_commit() {
    asm volatile("cp.async.commit_group;" ::: "memory");
}
__device__ __forceinline__ void cp_wait0() {
    asm volatile("cp.async.wait_group 0;" ::: "memory");
}

// =====================================================================
// Quantum circuit helper
// =====================================================================
__device__ __forceinline__ void circuit_feats(const float* __restrict__ U,
                                              const float* cry, const float* sry,
                                              int pauli, float* feats)
{
    float sr[16], si[16];
    #pragma unroll
    for (int i = 0; i < 16; i++) { sr[i] = 0.f; si[i] = 0.f; }
    sr[0] = 1.f;

    #pragma unroll
    for (int l = 0; l < NL; l++) {
        #pragma unroll
        for (int q = 0; q < NQ; q++) {
            const int m = 8 >> q;
            const float cc = cry[q], ss = sry[q];
            #pragma unroll
            for (int g = 0; g < 8; g++) {
                const int i0 = ((g & ~(m - 1)) << 1) | (g & (m - 1));
                const int i1 = i0 | m;
                const float r0 = sr[i0], r1 = sr[i1];
                const float q0 = si[i0], q1 = si[i1];
                sr[i0] = cc * r0 - ss * r1;  sr[i1] = ss * r0 + cc * r1;
                si[i0] = cc * q0 - ss * q1;  si[i1] = ss * q0 + cc * q1;
            }
        }
        #pragma unroll
        for (int q = 0; q < NQ; q++) {
            const float* u = U + (l * NQ + q) * 8;
            const float u00r = u[0], u00i = u[1], u01r = u[2], u01i = u[3];
            const float u10r = u[4], u10i = u[5], u11r = u[6], u11i = u[7];
            const int m = 8 >> q;
            #pragma unroll
            for (int g = 0; g < 8; g++) {
                const int i0 = ((g & ~(m - 1)) << 1) | (g & (m - 1));
                const int i1 = i0 | m;
                const float a0r = sr[i0], a0i = si[i0];
                const float a1r = sr[i1], a1i = si[i1];
                sr[i0] = u00r * a0r - u00i * a0i + u01r * a1r - u01i * a1i;
                si[i0] = u00r * a0i + u00i * a0r + u01r * a1i + u01i * a1r;
                sr[i1] = u10r * a0r - u10i * a0i + u11r * a1r - u11i * a1i;
                si[i1] = u10r * a0i + u10i * a0r + u11r * a1i + u11i * a1r;
            }
        }
        #pragma unroll
        for (int q = 0; q < NQ; q++) {
            const int mc = 8 >> q;
            const int mt = 8 >> ((q + 1) & 3);
            #pragma unroll
            for (int i = 0; i < 16; i++) {
                if ((i & mc) && !(i & mt)) {
                    const int jx = i | mt;
                    float t0 = sr[i]; sr[i] = sr[jx]; sr[jx] = t0;
                    float t1 = si[i]; si[i] = si[jx]; si[jx] = t1;
                }
            }
        }
    }

    #pragma unroll
    for (int q = 0; q < NQ; q++) {
        const int m = 8 >> q;
        float acc = 0.f;
        #pragma unroll
        for (int g = 0; g < 8; g++) {
            const int i0 = ((g & ~(m - 1)) << 1) | (g & (m - 1));
            const int i1 = i0 | m;
            if (pauli == 0)      acc += sr[i0] * sr[i1] + si[i0] * si[i1];
            else if (pauli == 1) acc += sr[i0] * si[i1] - si[i0] * sr[i1];
            else acc += sr[i0] * sr[i0] + si[i0] * si[i0] - sr[i1] * sr[i1] - si[i1] * si[i1];
        }
        feats[q] = (pauli == 2) ? acc : 2.f * acc;
    }
}

// =====================================================================
// Fused small kernel.
//  blocks [0, 6144): prep, one (p, c) pair each; tw/sw rows in smem.
//  blocks [6144, 6160): quantum circuit + readout MLP -> g_mod.
// =====================================================================
#define PREP_BLOCKS (PRED * CF)   // 6144

__global__ __launch_bounds__(256) void qres_small(
    const float* __restrict__ x,
    const float* __restrict__ dw,
    const float* __restrict__ tW,  const float* __restrict__ tb_,
    const float* __restrict__ sW,  const float* __restrict__ sb_,
    const float* __restrict__ alpha,
    const float* __restrict__ lW,  const float* __restrict__ lb,
    const float* __restrict__ wx,  const float* __restrict__ wy,
    const float* __restrict__ wz,
    const float* __restrict__ W1,  const float* __restrict__ b1v,
    const float* __restrict__ W2,  const float* __restrict__ b2v)
{
    const int bid = blockIdx.x;
    const int tid = threadIdx.x;

    if (bid < PREP_BLOCKS) {
        // ----------------- PREP path -----------------
        __shared__ float ker[32];
        __shared__ float twsh[SEQ], swsh[SEQ];
        const int p = bid >> 6;
        const int c = bid & (CF - 1);

        if (tid < 32) {
            const float val = (tid < KK) ? dw[c * KK + tid] : -1e30f;
            float mx = val;
            #pragma unroll
            for (int off = 16; off > 0; off >>= 1)
                mx = fmaxf(mx, __shfl_xor_sync(0xFFFFFFFFu, mx, off));
            float e = (tid < KK) ? expf(val - mx) : 0.f;
            float s = e;
            #pragma unroll
            for (int off = 16; off > 0; off >>= 1)
                s += __shfl_xor_sync(0xFFFFFFFFu, s, off);
            if (tid < 32) ker[tid] = (tid < KK) ? (e / s) : 0.f;
        }
        if (tid < SEQ) {
            twsh[tid] = tW[p * SEQ + tid];
            swsh[tid] = sW[p * SEQ + tid];
        }
        __syncthreads();

        const int j = tid;
        if (j >= SEQ) return;

        const float a  = 1.f / (1.f + expf(-alpha[0]));
        const float ia = 1.f - a;

        float accD = 0.f, accS = 0.f;
        if (j == 0) {
            #pragma unroll 1
            for (int k = 0; k <= PAD; k++) {
                const float kk = ker[k];
                for (int l = 0; l <= PAD - k; l++) {
                    accD += kk * (ia * twsh[l] - a * swsh[l]);
                    accS += kk * swsh[l];
                }
            }
        } else if (j == SEQ - 1) {
            #pragma unroll 1
            for (int k = PAD; k < KK; k++) {
                const float kk = ker[k];
                for (int l = (SEQ - 1 + PAD) - k; l < SEQ; l++) {
                    accD += kk * (ia * twsh[l] - a * swsh[l]);
                    accS += kk * swsh[l];
                }
            }
        } else {
            #pragma unroll
            for (int k = 0; k < KK; k++) {
                const int l = j + PAD - k;
                if (l >= 0 && l < SEQ) {
                    const float kk = ker[k];
                    accD += kk * (ia * twsh[l] - a * swsh[l]);
                    accS += kk * swsh[l];
                }
            }
        }

        float* Gf = reinterpret_cast<float*>(g_G4);
        float* Hf = reinterpret_cast<float*>(g_H4);
        const float swj = swsh[j];
        Gf[(p * SEQ + j) * CF + c] = a * swj + accD;
        Hf[(p * SEQ + j) * CF + c] = a * (swj - accS);

        if (c == 0 && j == 0) {
            g_b0[p] = a * sb_[p] + ia * tb_[p];
            g_b1[p] = a * sb_[p];
        }
        return;
    }

    // ----------------- QUANTUM path -----------------
    __shared__ float Us[3][NL * NQ * 8];
    __shared__ float sW1[12 * 12], sb1[12], sW2[96 * 12], sb2[96];

    if (tid < 36) {
        const int t = tid / 12, rem = tid % 12;
        const int l = rem / 4, q = rem % 4;
        const float* w = (t == 0) ? wx : ((t == 1) ? wy : wz);
        const float phi = w[(l * NQ + q) * 3 + 0];
        const float th  = w[(l * NQ + q) * 3 + 1];
        const float om  = w[(l * NQ + q) * 3 + 2];
        float st, ct;  sincosf(0.5f * th, &st, &ct);
        float sap, cap; sincosf(0.5f * (phi + om), &sap, &cap);
        float sam, cam; sincosf(0.5f * (phi - om), &sam, &cam);
        float* U = &Us[t][rem * 8];
        U[0] =  cap * ct;  U[1] = -sap * ct;
        U[2] = -cam * st;  U[3] = -sam * st;
        U[4] =  cam * st;  U[5] = -sam * st;
        U[6] =  cap * ct;  U[7] =  sap * ct;
    }
    for (int i = tid; i < 144;  i += 256) sW1[i] = W1[i];
    for (int i = tid; i < 1152; i += 256) sW2[i] = W2[i];
    if (tid < 12) sb1[tid] = b1v[tid];
    if (tid < 96) sb2[tid] = b2v[tid];
    __syncthreads();

    const int b = (bid - PREP_BLOCKS) * 256 + tid;
    if (b >= NB) return;

    const int LAGS[NLAG] = {167, 166, 165, 164, 163, 162, 145, 144, 143, 1, 0};
    float lag[NLAG];
    const float* xb = x + (size_t)b * SEQ * CF + (CF - 1);
    #pragma unroll
    for (int i = 0; i < NLAG; i++) lag[i] = xb[LAGS[i] * CF];

    const float PI_F = 3.14159265358979323846f;
    float cry[NQ], sry[NQ];
    #pragma unroll
    for (int q = 0; q < NQ; q++) {
        float acc = lb[q];
        #pragma unroll
        for (int i = 0; i < NLAG; i++) acc += lag[i] * lW[q * NLAG + i];
        const float qin = tanhf(acc) * PI_F;
        sincosf(0.5f * qin, &sry[q], &cry[q]);
    }

    float feats[12];
    circuit_feats(&Us[0][0], cry, sry, 0, &feats[0]);
    circuit_feats(&Us[1][0], cry, sry, 1, &feats[4]);
    circuit_feats(&Us[2][0], cry, sry, 2, &feats[8]);

    float h[12];
    #pragma unroll
    for (int i = 0; i < 12; i++) {
        float acc = sb1[i];
        #pragma unroll
        for (int jj = 0; jj < 12; jj++) acc += feats[jj] * sW1[i * 12 + jj];
        h[i] = fmaxf(acc, 0.f);
    }
    #pragma unroll 4
    for (int p = 0; p < PRED; p++) {
        float acc = sb2[p];
        #pragma unroll
        for (int i = 0; i < 12; i++) acc += h[i] * sW2[p * 12 + i];
        g_mod[b * PRED + p] = tanhf(acc);
    }
}

// =====================================================================
// Main GEMM: 512 threads, block tile 64b x 96p x 4c, thread tile 4b x 3p x 4c.
// cp.async double-buffered K-panels of 4. f32x2 math.
// grid: (16 cg, 64 bt)
// =====================================================================
#define KP 4
#define NPANEL (SEQ / KP)   // 42
#define CG4 (CF / 4)        // 16

__global__ __launch_bounds__(512, 1) void qres_main(const float* __restrict__ x,
                                                    float* __restrict__ out)
{
    const int cg = blockIdx.x;   // 0..15
    const int bt = blockIdx.y;   // 0..63
    const int b0 = bt * 64;

    const int tid = threadIdx.x;
    const int tb = tid & 15;     // 0..15 (b)
    const int tp = tid >> 4;     // 0..31 (p)

    __shared__ ulonglong2 Xs[2][KP][64];
    __shared__ ulonglong2 Gs[2][KP][PRED];
    __shared__ ulonglong2 Hs[2][KP][PRED];

    const ulonglong2* xg = reinterpret_cast<const ulonglong2*>(x);
    const ulonglong2* Gg = reinterpret_cast<const ulonglong2*>(g_G4);
    const ulonglong2* Hg = reinterpret_cast<const ulonglong2*>(g_H4);

    u64 aG[4][3][2], aH[4][3][2];
    #pragma unroll
    for (int bi = 0; bi < 4; bi++)
        #pragma unroll
        for (int pi = 0; pi < 3; pi++) {
            aG[bi][pi][0] = 0ull; aG[bi][pi][1] = 0ull;
            aH[bi][pi][0] = 0ull; aH[bi][pi][1] = 0ull;
        }

    // loader roles
    const bool loadX = (tid < 256);
    const int xk0 = tid >> 6;          // 0..3 (valid when loadX)
    const int xb0 = tid & 63;
    const bool loadG = (tid >= 128);
    const int gt = tid - 128;          // 0..383
    const int gk = gt / PRED;          // 0..3
    const int gp = gt - gk * PRED;     // 0..95

    const ulonglong2* xp = xg + ((size_t)(b0 + xb0) * SEQ + xk0) * CG4 + cg;
    const ulonglong2* Gp = Gg + ((size_t)gp * SEQ + gk) * CG4 + cg;
    const ulonglong2* Hp = Hg + ((size_t)gp * SEQ + gk) * CG4 + cg;

    const uint32_t sX0 = (uint32_t)__cvta_generic_to_shared(&Xs[0][xk0][xb0]);
    const uint32_t sX1 = (uint32_t)__cvta_generic_to_shared(&Xs[1][xk0][xb0]);
    const uint32_t sG0 = (uint32_t)__cvta_generic_to_shared(&Gs[0][gk][gp]);
    const uint32_t sG1 = (uint32_t)__cvta_generic_to_shared(&Gs[1][gk][gp]);
    const uint32_t sH0 = (uint32_t)__cvta_generic_to_shared(&Hs[0][gk][gp]);
    const uint32_t sH1 = (uint32_t)__cvta_generic_to_shared(&Hs[1][gk][gp]);

    // prologue: panel 0 -> buffer 0
    if (loadX) cp16(sX0, xp);
    if (loadG) { cp16(sG0, Gp); cp16(sH0, Hp); }
    cp_commit();
    if (loadX) xp += KP * CG4;
    if (loadG) { Gp += KP * CG4; Hp += KP * CG4; }

    for (int pn = 0; pn < NPANEL; pn++) {
        const int buf = pn & 1;
        cp_wait0();
        __syncthreads();   // panel pn visible; previous compute on buf^1 done

        if (pn + 1 < NPANEL) {
            if (loadX) { cp16(buf ? sX0 : sX1, xp); xp += KP * CG4; }
            if (loadG) { cp16(buf ? sG0 : sG1, Gp); Gp += KP * CG4;
                         cp16(buf ? sH0 : sH1, Hp); Hp += KP * CG4; }
        }
        cp_commit();

        #pragma unroll
        for (int kj = 0; kj < KP; kj++) {
            ulonglong2 xf[4];
            #pragma unroll
            for (int bi = 0; bi < 4; bi++) xf[bi] = Xs[buf][kj][tb + 16 * bi];
            #pragma unroll
            for (int pi = 0; pi < 3; pi++) {
                const ulonglong2 gf = Gs[buf][kj][tp + 32 * pi];
                const ulonglong2 hf = Hs[buf][kj][tp + 32 * pi];
                #pragma unroll
                for (int bi = 0; bi < 4; bi++) {
                    fma2(aG[bi][pi][0], xf[bi].x, gf.x);
                    fma2(aG[bi][pi][1], xf[bi].y, gf.y);
                    fma2(aH[bi][pi][0], xf[bi].x, hf.x);
                    fma2(aH[bi][pi][1], xf[bi].y, hf.y);
                }
            }
        }
    }

    // epilogue
    ulonglong2* og = reinterpret_cast<ulonglong2*>(out);
    #pragma unroll
    for (int bi = 0; bi < 4; bi++) {
        const int b = b0 + tb + 16 * bi;
        #pragma unroll
        for (int pi = 0; pi < 3; pi++) {
            const int p = tp + 32 * pi;
            const float m   = g_mod[b * PRED + p];
            const float add = g_b0[p] + m * g_b1[p];
            const u64 m2  = pack2(m, m);
            const u64 ad2 = pack2(add, add);
            u64 r0 = aG[bi][pi][0], r1 = aG[bi][pi][1];
            fma2(r0, m2, aH[bi][pi][0]);
            fma2(r1, m2, aH[bi][pi][1]);
            add2(r0, ad2);
            add2(r1, ad2);
            ulonglong2 st; st.x = r0; st.y = r1;
            og[((size_t)b * PRED + p) * CG4 + cg] = st;
        }
    }
}

// =====================================================================
// Launch
// =====================================================================
extern "C" void kernel_launch(void* const* d_in, const int* in_sizes, int n_in,
                              void* d_out, int out_size)
{
    const float* x      = (const float*)d_in[0];
    const float* dw     = (const float*)d_in[1];
    const float* tW     = (const float*)d_in[2];
    const float* tb_    = (const float*)d_in[3];
    const float* sW     = (const float*)d_in[4];
    const float* sb_    = (const float*)d_in[5];
    const float* lagcW  = (const float*)d_in[6];
    const float* lagcb  = (const float*)d_in[7];
    const float* wx     = (const float*)d_in[8];
    const float* wy     = (const float*)d_in[9];
    const float* wz     = (const float*)d_in[10];
    const float* roW1   = (const float*)d_in[11];
    const float* rob1   = (const float*)d_in[12];
    const float* roW2   = (const float*)d_in[13];
    const float* rob2   = (const float*)d_in[14];
    const float* alpha  = (const float*)d_in[15];
    float* out = (float*)d_out;

    qres_small<<<PREP_BLOCKS + NB / 256, 256>>>(
        x, dw, tW, tb_, sW, sb_, alpha,
        lagcW, lagcb, wx, wy, wz, roW1, rob1, roW2, rob2);
    qres_main<<<dim3(CG4, NB / 64), 512>>>(x, out);
}

// round 16
// speedup vs baseline: 1.8701x; 1.8498x over previous
#include <cuda_runtime.h>
#include <cstdint>

// ---------------- Problem constants ----------------
#define NB    4096
#define SEQ   168      // = 21 * 8, exact k8 steps
#define NK8   21
#define PRED  96
#define CF    64
#define KK    25
#define PAD   12
#define NQ    4
#define NL    3
#define NLAG  11

// ---------------- Scratch (device globals) ----------------
// A fragments: [c][s][mt][lane] float4 = (a0,a1,a2,a3) tf32 bits
__device__ float4 g_A[(size_t)CF * NK8 * (NB / 16) * 32];
// B fragments: [c][s][nt][lane] float2 = (b0,b1), n interleaved = 2p+gh
__device__ float2 g_Bf[(size_t)CF * NK8 * 24 * 32];
// o_t[c][b][p]
__device__ float4 g_ot4[(size_t)CF * NB * (PRED / 4)];
__device__ float  g_modT[PRED * NB];     // mod transposed [p][b]
__device__ float  g_b0[PRED];
__device__ float  g_b1[PRED];

// ---------------- helpers ----------------
__device__ __forceinline__ uint32_t to_tf32(float f) {
    uint32_t u; asm("cvt.rna.tf32.f32 %0, %1;" : "=r"(u) : "f"(f)); return u;
}
__device__ __forceinline__ void cp16(uint32_t smem_dst, const void* gptr) {
    asm volatile("cp.async.cg.shared.global [%0], [%1], 16;"
                 :: "r"(smem_dst), "l"(__cvta_generic_to_global(gptr)) : "memory");
}
__device__ __forceinline__ void cp_commit() {
    asm volatile("cp.async.commit_group;" ::: "memory");
}
__device__ __forceinline__ void cp_wait0() {
    asm volatile("cp.async.wait_group 0;" ::: "memory");
}
__device__ __forceinline__ void mma_tf32(float* d, const uint32_t* a, const uint32_t* b) {
    asm volatile("mma.sync.aligned.m16n8k8.row.col.f32.tf32.tf32.f32 "
        "{%0,%1,%2,%3}, {%4,%5,%6,%7}, {%8,%9}, {%0,%1,%2,%3};"
        : "+f"(d[0]), "+f"(d[1]), "+f"(d[2]), "+f"(d[3])
        : "r"(a[0]), "r"(a[1]), "r"(a[2]), "r"(a[3]), "r"(b[0]), "r"(b[1]));
}

// =====================================================================
// Kernel 1: x[b][j][c] -> A fragments (tf32)
// CTA = one 16-row m-tile (mt), loops over 21 k-steps.
// a0 = x[mt*16 + l/4][s*8 + l%4][c], a1 = row+8, a2 = col+4, a3 = both.
// =====================================================================
__global__ __launch_bounds__(256) void qres_afrag(const float* __restrict__ x)
{
    __shared__ float sx[16 * 8 * 65];    // [bb][jj][c], pad 65
    const int mt  = blockIdx.x;          // 0..255
    const int b0  = mt * 16;
    const int tid = threadIdx.x;

    const float4* x4 = reinterpret_cast<const float4*>(x);

    for (int s = 0; s < NK8; s++) {
        // load chunk x[b0..b0+16)[s*8..s*8+8)[all c]
        #pragma unroll
        for (int i = tid; i < 2048; i += 256) {
            const int bb = i >> 7;
            const int jj = (i >> 4) & 7;
            const int c4 = i & 15;
            const float4 v = x4[((size_t)(b0 + bb) * SEQ + s * 8 + jj) * 16 + c4];
            float* dst = &sx[(bb * 8 + jj) * 65 + c4 * 4];
            dst[0] = v.x; dst[1] = v.y; dst[2] = v.z; dst[3] = v.w;
        }
        __syncthreads();

        // write fragments
        #pragma unroll
        for (int i = tid; i < 2048; i += 256) {
            const int c = i >> 5;
            const int l = i & 31;
            const int row = l >> 2;
            const int kc  = l & 3;
            const uint32_t a0 = to_tf32(sx[(row * 8 + kc) * 65 + c]);
            const uint32_t a1 = to_tf32(sx[((row + 8) * 8 + kc) * 65 + c]);
            const uint32_t a2 = to_tf32(sx[(row * 8 + kc + 4) * 65 + c]);
            const uint32_t a3 = to_tf32(sx[((row + 8) * 8 + kc + 4) * 65 + c]);
            float4 v;
            v.x = __uint_as_float(a0); v.y = __uint_as_float(a1);
            v.z = __uint_as_float(a2); v.w = __uint_as_float(a3);
            g_A[(((size_t)c * NK8 + s) * 256 + mt) * 32 + l] = v;
        }
        __syncthreads();
    }
}

// =====================================================================
// Quantum circuit helper
// =====================================================================
__device__ __forceinline__ void circuit_feats(const float* __restrict__ U,
                                              const float* cry, const float* sry,
                                              int pauli, float* feats)
{
    float sr[16], si[16];
    #pragma unroll
    for (int i = 0; i < 16; i++) { sr[i] = 0.f; si[i] = 0.f; }
    sr[0] = 1.f;

    #pragma unroll
    for (int l = 0; l < NL; l++) {
        #pragma unroll
        for (int q = 0; q < NQ; q++) {
            const int m = 8 >> q;
            const float cc = cry[q], ss = sry[q];
            #pragma unroll
            for (int g = 0; g < 8; g++) {
                const int i0 = ((g & ~(m - 1)) << 1) | (g & (m - 1));
                const int i1 = i0 | m;
                const float r0 = sr[i0], r1 = sr[i1];
                const float q0 = si[i0], q1 = si[i1];
                sr[i0] = cc * r0 - ss * r1;  sr[i1] = ss * r0 + cc * r1;
                si[i0] = cc * q0 - ss * q1;  si[i1] = ss * q0 + cc * q1;
            }
        }
        #pragma unroll
        for (int q = 0; q < NQ; q++) {
            const float* u = U + (l * NQ + q) * 8;
            const float u00r = u[0], u00i = u[1], u01r = u[2], u01i = u[3];
            const float u10r = u[4], u10i = u[5], u11r = u[6], u11i = u[7];
            const int m = 8 >> q;
            #pragma unroll
            for (int g = 0; g < 8; g++) {
                const int i0 = ((g & ~(m - 1)) << 1) | (g & (m - 1));
                const int i1 = i0 | m;
                const float a0r = sr[i0], a0i = si[i0];
                const float a1r = sr[i1], a1i = si[i1];
                sr[i0] = u00r * a0r - u00i * a0i + u01r * a1r - u01i * a1i;
                si[i0] = u00r * a0i + u00i * a0r + u01r * a1i + u01i * a1r;
                sr[i1] = u10r * a0r - u10i * a0i + u11r * a1r - u11i * a1i;
                si[i1] = u10r * a0i + u10i * a0r + u11r * a1i + u11i * a1r;
            }
        }
        #pragma unroll
        for (int q = 0; q < NQ; q++) {
            const int mc = 8 >> q;
            const int mt = 8 >> ((q + 1) & 3);
            #pragma unroll
            for (int i = 0; i < 16; i++) {
                if ((i & mc) && !(i & mt)) {
                    const int jx = i | mt;
                    float t0 = sr[i]; sr[i] = sr[jx]; sr[jx] = t0;
                    float t1 = si[i]; si[i] = si[jx]; si[jx] = t1;
                }
            }
        }
    }

    #pragma unroll
    for (int q = 0; q < NQ; q++) {
        const int m = 8 >> q;
        float acc = 0.f;
        #pragma unroll
        for (int g = 0; g < 8; g++) {
            const int i0 = ((g & ~(m - 1)) << 1) | (g & (m - 1));
            const int i1 = i0 | m;
            if (pauli == 0)      acc += sr[i0] * sr[i1] + si[i0] * si[i1];
            else if (pauli == 1) acc += sr[i0] * si[i1] - si[i0] * sr[i1];
            else acc += sr[i0] * sr[i0] + si[i0] * si[i0] - sr[i1] * sr[i1] - si[i1] * si[i1];
        }
        feats[q] = (pauli == 2) ? acc : 2.f * acc;
    }
}

// =====================================================================
// Kernel 2: prep (blocks [0,6144)) writes B fragments (GH interleaved),
//           quantum (blocks [6144,6160)) writes g_modT.
// =====================================================================
#define PREP_BLOCKS (PRED * CF)   // 6144

__global__ __launch_bounds__(256) void qres_small(
    const float* __restrict__ x,
    const float* __restrict__ dw,
    const float* __restrict__ tW,  const float* __restrict__ tb_,
    const float* __restrict__ sW,  const float* __restrict__ sb_,
    const float* __restrict__ alpha,
    const float* __restrict__ lW,  const float* __restrict__ lb,
    const float* __restrict__ wx,  const float* __restrict__ wy,
    const float* __restrict__ wz,
    const float* __restrict__ W1,  const float* __restrict__ b1v,
    const float* __restrict__ W2,  const float* __restrict__ b2v)
{
    const int bid = blockIdx.x;
    const int tid = threadIdx.x;

    if (bid < PREP_BLOCKS) {
        __shared__ float ker[32];
        __shared__ float twsh[SEQ], swsh[SEQ];
        const int p = bid >> 6;
        const int c = bid & (CF - 1);

        if (tid < 32) {
            const float val = (tid < KK) ? dw[c * KK + tid] : -1e30f;
            float mx = val;
            #pragma unroll
            for (int off = 16; off > 0; off >>= 1)
                mx = fmaxf(mx, __shfl_xor_sync(0xFFFFFFFFu, mx, off));
            float e = (tid < KK) ? expf(val - mx) : 0.f;
            float s = e;
            #pragma unroll
            for (int off = 16; off > 0; off >>= 1)
                s += __shfl_xor_sync(0xFFFFFFFFu, s, off);
            ker[tid] = (tid < KK) ? (e / s) : 0.f;
        }
        if (tid < SEQ) {
            twsh[tid] = tW[p * SEQ + tid];
            swsh[tid] = sW[p * SEQ + tid];
        }
        __syncthreads();

        const int j = tid;
        if (j >= SEQ) return;

        const float a  = 1.f / (1.f + expf(-alpha[0]));
        const float ia = 1.f - a;

        float accD = 0.f, accS = 0.f;
        if (j == 0) {
            #pragma unroll 1
            for (int k = 0; k <= PAD; k++) {
                const float kk = ker[k];
                for (int l = 0; l <= PAD - k; l++) {
                    accD += kk * (ia * twsh[l] - a * swsh[l]);
                    accS += kk * swsh[l];
                }
            }
        } else if (j == SEQ - 1) {
            #pragma unroll 1
            for (int k = PAD; k < KK; k++) {
                const float kk = ker[k];
                for (int l = (SEQ - 1 + PAD) - k; l < SEQ; l++) {
                    accD += kk * (ia * twsh[l] - a * swsh[l]);
                    accS += kk * swsh[l];
                }
            }
        } else {
            #pragma unroll
            for (int k = 0; k < KK; k++) {
                const int l = j + PAD - k;
                if (l >= 0 && l < SEQ) {
                    const float kk = ker[k];
                    accD += kk * (ia * twsh[l] - a * swsh[l]);
                    accS += kk * swsh[l];
                }
            }
        }

        const float swj = swsh[j];
        const float gv = a * swj + accD;         // G[c][p][j]
        const float hv = a * (swj - accS);       // H[c][p][j]

        // fragment store: n = 2p + gh, s = j/8, lane = (n%8)*4 + (j%8)%4, reg = (j%8)/4
        float* Bf = reinterpret_cast<float*>(g_Bf);
        const int s  = j >> 3;
        const int jr = j & 7;
        const int reg = jr >> 2;
        const int kc  = jr & 3;
        {
            const int n = 2 * p;
            const size_t idx = ((((size_t)c * NK8 + s) * 24 + (n >> 3)) * 32
                               + (n & 7) * 4 + kc) * 2 + reg;
            Bf[idx] = __uint_as_float(to_tf32(gv));
        }
        {
            const int n = 2 * p + 1;
            const size_t idx = ((((size_t)c * NK8 + s) * 24 + (n >> 3)) * 32
                               + (n & 7) * 4 + kc) * 2 + reg;
            Bf[idx] = __uint_as_float(to_tf32(hv));
        }

        if (c == 0 && j == 0) {
            g_b0[p] = a * sb_[p] + ia * tb_[p];
            g_b1[p] = a * sb_[p];
        }
        return;
    }

    // ----------------- QUANTUM path -----------------
    __shared__ float Us[3][NL * NQ * 8];
    __shared__ float sW1[12 * 12], sb1[12], sW2[96 * 12], sb2[96];

    if (tid < 36) {
        const int t = tid / 12, rem = tid % 12;
        const int l = rem / 4, q = rem % 4;
        const float* w = (t == 0) ? wx : ((t == 1) ? wy : wz);
        const float phi = w[(l * NQ + q) * 3 + 0];
        const float th  = w[(l * NQ + q) * 3 + 1];
        const float om  = w[(l * NQ + q) * 3 + 2];
        float st, ct;  sincosf(0.5f * th, &st, &ct);
        float sap, cap; sincosf(0.5f * (phi + om), &sap, &cap);
        float sam, cam; sincosf(0.5f * (phi - om), &sam, &cam);
        float* U = &Us[t][rem * 8];
        U[0] =  cap * ct;  U[1] = -sap * ct;
        U[2] = -cam * st;  U[3] = -sam * st;
        U[4] =  cam * st;  U[5] = -sam * st;
        U[6] =  cap * ct;  U[7] =  sap * ct;
    }
    for (int i = tid; i < 144;  i += 256) sW1[i] = W1[i];
    for (int i = tid; i < 1152; i += 256) sW2[i] = W2[i];
    if (tid < 12) sb1[tid] = b1v[tid];
    if (tid < 96) sb2[tid] = b2v[tid];
    __syncthreads();

    const int b = (bid - PREP_BLOCKS) * 256 + tid;
    if (b >= NB) return;

    const int LAGS[NLAG] = {167, 166, 165, 164, 163, 162, 145, 144, 143, 1, 0};
    float lag[NLAG];
    const float* xb = x + (size_t)b * SEQ * CF + (CF - 1);
    #pragma unroll
    for (int i = 0; i < NLAG; i++) lag[i] = xb[LAGS[i] * CF];

    const float PI_F = 3.14159265358979323846f;
    float cry[NQ], sry[NQ];
    #pragma unroll
    for (int q = 0; q < NQ; q++) {
        float acc = lb[q];
        #pragma unroll
        for (int i = 0; i < NLAG; i++) acc += lag[i] * lW[q * NLAG + i];
        const float qin = tanhf(acc) * PI_F;
        sincosf(0.5f * qin, &sry[q], &cry[q]);
    }

    float feats[12];
    circuit_feats(&Us[0][0], cry, sry, 0, &feats[0]);
    circuit_feats(&Us[1][0], cry, sry, 1, &feats[4]);
    circuit_feats(&Us[2][0], cry, sry, 2, &feats[8]);

    float h[12];
    #pragma unroll
    for (int i = 0; i < 12; i++) {
        float acc = sb1[i];
        #pragma unroll
        for (int jj = 0; jj < 12; jj++) acc += feats[jj] * sW1[i * 12 + jj];
        h[i] = fmaxf(acc, 0.f);
    }
    #pragma unroll 4
    for (int p = 0; p < PRED; p++) {
        float acc = sb2[p];
        #pragma unroll
        for (int i = 0; i < 12; i++) acc += h[i] * sW2[p * 12 + i];
        g_modT[(size_t)p * NB + b] = tanhf(acc);   // transposed: coalesced in b
    }
}

// =====================================================================
// Kernel 3: mma.sync tf32 GEMM.
// CTA: (bt 0..31, c 0..63): 128 b-rows x 192 n (= 96 p x {G,H} interleaved).
// 8 warps = 2(m) x 4(n); warp tile m64 x n48; 21 k8 steps in 7 chunks of 3.
// =====================================================================
#define SCH      3
#define CHUNKS   7
#define ABYTES   (SCH * 8 * 32 * 16)     // 12288
#define BBYTES   (SCH * 24 * 32 * 8)     // 18432
#define BUFBYTES (ABYTES + BBYTES)       // 30720
#define GEMM_SMEM (2 * BUFBYTES)         // 61440

__global__ __launch_bounds__(256) void qres_gemm()
{
    extern __shared__ char smc[];
    const uint32_t smb = (uint32_t)__cvta_generic_to_shared(smc);
    const int bt  = blockIdx.x;      // 0..31
    const int c   = blockIdx.y;      // 0..63
    const int tid = threadIdx.x;
    const int wid  = tid >> 5;
    const int lane = tid & 31;
    const int wm = wid >> 2;         // 0..1
    const int wn = wid & 3;          // 0..3

    float d[4][6][4];
    #pragma unroll
    for (int i = 0; i < 4; i++)
        #pragma unroll
        for (int j = 0; j < 6; j++)
            #pragma unroll
            for (int r = 0; r < 4; r++) d[i][j][r] = 0.f;

    const float4* Ag = g_A;
    const char*   Bg = reinterpret_cast<const char*>(g_Bf);

    // ---- chunk loader ----
    #define LOAD_CHUNK(ch, buf)                                                     \
    do {                                                                            \
        const int s0_ = (ch) * SCH;                                                 \
        for (int i_ = tid; i_ < SCH * 256; i_ += 256) {                             \
            const int sl_ = i_ >> 8, off_ = i_ & 255;                               \
            cp16(smb + (buf) * BUFBYTES + (sl_ * 256 + off_) * 16,                  \
                 Ag + (((size_t)c * NK8 + s0_ + sl_) * 256 + bt * 8) * 32 + off_);  \
        }                                                                           \
        for (int i_ = tid; i_ < SCH * 384; i_ += 256) {                             \
            const int sl_ = i_ / 384, off_ = i_ % 384;                              \
            cp16(smb + (buf) * BUFBYTES + ABYTES + (sl_ * 384 + off_) * 16,         \
                 Bg + (((size_t)c * NK8 + s0_ + sl_) * 24 * 32) * 8 + off_ * 16);   \
        }                                                                           \
    } while (0)

    LOAD_CHUNK(0, 0);
    cp_commit();

    for (int ch = 0; ch < CHUNKS; ch++) {
        const int buf = ch & 1;
        cp_wait0();
        __syncthreads();
        if (ch + 1 < CHUNKS) LOAD_CHUNK(ch + 1, buf ^ 1);
        cp_commit();

        #pragma unroll
        for (int sl = 0; sl < SCH; sl++) {
            uint32_t a[4][4];
            uint32_t bfr[6][2];
            #pragma unroll
            for (int i = 0; i < 4; i++) {
                const uint32_t addr = smb + buf * BUFBYTES
                                    + ((sl * 8 + wm * 4 + i) * 32 + lane) * 16;
                asm volatile("ld.shared.v4.b32 {%0,%1,%2,%3}, [%4];"
                    : "=r"(a[i][0]), "=r"(a[i][1]), "=r"(a[i][2]), "=r"(a[i][3])
                    : "r"(addr));
            }
            #pragma unroll
            for (int j = 0; j < 6; j++) {
                const uint32_t addr = smb + buf * BUFBYTES + ABYTES
                                    + ((sl * 24 + wn * 6 + j) * 32 + lane) * 8;
                asm volatile("ld.shared.v2.b32 {%0,%1}, [%2];"
                    : "=r"(bfr[j][0]), "=r"(bfr[j][1]) : "r"(addr));
            }
            #pragma unroll
            for (int i = 0; i < 4; i++)
                #pragma unroll
                for (int j = 0; j < 6; j++)
                    mma_tf32(d[i][j], a[i], bfr[j]);
        }
    }
    #undef LOAD_CHUNK

    // ---- epilogue: combine G/H with mod, stage, coalesced store ----
    __syncthreads();
    float* stage = reinterpret_cast<float*>(smc);   // [128][100]

    #pragma unroll
    for (int j = 0; j < 6; j++) {
        const int p = (wn * 6 + j) * 4 + (lane & 3);
        const float bb0 = g_b0[p];
        const float bb1 = g_b1[p];
        const float* mrow = g_modT + (size_t)p * NB + bt * 128;
        #pragma unroll
        for (int i = 0; i < 4; i++) {
            const int r0 = wm * 64 + i * 16 + (lane >> 2);
            const float m0 = mrow[r0];
            const float m1 = mrow[r0 + 8];
            stage[r0 * 100 + p]       = d[i][j][0] + m0 * d[i][j][1] + bb0 + m0 * bb1;
            stage[(r0 + 8) * 100 + p] = d[i][j][2] + m1 * d[i][j][3] + bb0 + m1 * bb1;
        }
    }
    __syncthreads();

    float4* ot = g_ot4 + ((size_t)c * NB + bt * 128) * (PRED / 4);
    for (int i = tid; i < 128 * (PRED / 4); i += 256) {
        const int r = i / 24, pg = i % 24;
        const float* s = &stage[r * 100 + pg * 4];
        ot[(size_t)r * 24 + pg] = make_float4(s[0], s[1], s[2], s[3]);
    }
}

// =====================================================================
// Kernel 4: pack o_t[c][b][p] -> out[b][p][c]
// =====================================================================
__global__ __launch_bounds__(256) void qres_pack(float* __restrict__ out)
{
    const int gid = blockIdx.x * 256 + threadIdx.x;   // 0 .. 4096*96-1
    const int b = gid / PRED;
    const int p = gid - b * PRED;

    const float* src = reinterpret_cast<const float*>(g_ot4) + (size_t)b * PRED + p;
    float4* o4 = reinterpret_cast<float4*>(out + ((size_t)b * PRED + p) * CF);
    const size_t plane = (size_t)NB * PRED;

    #pragma unroll 4
    for (int c4 = 0; c4 < 16; c4++) {
        float4 v;
        v.x = src[(size_t)(c4 * 4 + 0) * plane];
        v.y = src[(size_t)(c4 * 4 + 1) * plane];
        v.z = src[(size_t)(c4 * 4 + 2) * plane];
        v.w = src[(size_t)(c4 * 4 + 3) * plane];
        o4[c4] = v;
    }
}

// =====================================================================
// Launch
// =====================================================================
extern "C" void kernel_launch(void* const* d_in, const int* in_sizes, int n_in,
                              void* d_out, int out_size)
{
    const float* x      = (const float*)d_in[0];
    const float* dw     = (const float*)d_in[1];
    const float* tW     = (const float*)d_in[2];
    const float* tb_    = (const float*)d_in[3];
    const float* sW     = (const float*)d_in[4];
    const float* sb_    = (const float*)d_in[5];
    const float* lagcW  = (const float*)d_in[6];
    const float* lagcb  = (const float*)d_in[7];
    const float* wx     = (const float*)d_in[8];
    const float* wy     = (const float*)d_in[9];
    const float* wz     = (const float*)d_in[10];
    const float* roW1   = (const float*)d_in[11];
    const float* rob1   = (const float*)d_in[12];
    const float* roW2   = (const float*)d_in[13];
    const float* rob2   = (const float*)d_in[14];
    const float* alpha  = (const float*)d_in[15];
    float* out = (float*)d_out;

    cudaFuncSetAttribute(qres_gemm, cudaFuncAttributeMaxDynamicSharedMemorySize, GEMM_SMEM);

    qres_afrag<<<NB / 16, 256>>>(x);
    qres_small<<<PREP_BLOCKS + NB / 256, 256>>>(
        x, dw, tW, tb_, sW, sb_, alpha,
        lagcW, lagcb, wx, wy, wz, roW1, rob1, roW2, rob2);
    qres_gemm<<<dim3(32, CF), 256, GEMM_SMEM>>>();
    qres_pack<<<NB * PRED / 256, 256>>>(out);
}